// round 5
// baseline (speedup 1.0000x reference)
#include <cuda_runtime.h>
#include <math.h>

#define NUM_B 2
#define NUM_C 256
#define NUM_H 256
#define NUM_W 256
#define NUM_N 512
#define OUT_H 7
#define OUT_W 7
#define NBIN 49
#define HW (NUM_H * NUM_W)
#define CHW (NUM_C * HW)
#define C_HALF 128

#define MB_TOPN 1
#define MB_BOTN 2
#define MB_XT   4
#define MB_XB   8

__global__ __launch_bounds__(256, 6) void rroi_pool_kernel(
    const float* __restrict__ x,
    const float* __restrict__ boxes,
    float* __restrict__ out)
{
    __shared__ int4   s_off[NBIN];  // top f4 off, bottom f4 off, top extra, bottom extra
    __shared__ float4 s_wt[NBIN];   // lane weights for top float4
    __shared__ float4 s_wb[NBIN];   // lane weights for bottom float4
    __shared__ float2 s_wx[NBIN];   // scalar fallback weights (top, bottom)
    __shared__ int    s_meta[NBIN];

    const int roi  = blockIdx.x >> 1;
    const int half = blockIdx.x & 1;
    const int tid  = threadIdx.x;

    if (tid < NBIN) {
        const float* bx = boxes + roi * 5;
        float cx  = __fmul_rn(bx[0], 0.25f);
        float cy  = __fmul_rn(bx[1], 0.25f);
        float w   = __fmul_rn(bx[2], 0.25f);
        float h   = __fmul_rn(bx[3], 0.25f);
        float ang = __fmul_rn(bx[4], 0.017453292519943295f);

        float Sx = __fdiv_rn(w, 7.0f);
        float Sy = __fdiv_rn(h, 7.0f);
        float ca = cosf(ang);
        float sa = sinf(ang);

        const float dxc = -3.5f;
        const float dyc = -3.5f;

        float M00 = __fmul_rn(ca, Sx);
        float M01 = __fmul_rn(sa, Sy);
        float M02 = __fadd_rn(__fadd_rn(__fmul_rn(__fmul_rn(ca, Sx), dxc),
                                        __fmul_rn(__fmul_rn(sa, Sy), dyc)), cx);
        float M10 = __fmul_rn(-sa, Sx);
        float M11 = __fmul_rn(ca, Sy);
        float M12 = __fadd_rn(__fadd_rn(__fmul_rn(__fmul_rn(-sa, Sx), dxc),
                                        __fmul_rn(__fmul_rn(ca, Sy), dyc)), cy);

        int ph = tid / OUT_W;
        int pw = tid - ph * OUT_W;

        const float offx[4] = {0.f, 0.f, 1.f, 1.f};
        const float offy[4] = {0.f, 1.f, 0.f, 1.f};

        float minX =  3.0e38f, maxX = -3.0e38f;
        float minY =  3.0e38f, maxY = -3.0e38f;
        #pragma unroll
        for (int k = 0; k < 4; ++k) {
            float pwc = (float)pw + offx[k];
            float phc = (float)ph + offy[k];
            float X = __fadd_rn(__fadd_rn(__fmul_rn(M00, pwc), __fmul_rn(M01, phc)), M02);
            float Y = __fadd_rn(__fadd_rn(__fmul_rn(M10, pwc), __fmul_rn(M11, phc)), M12);
            minX = fminf(minX, X); maxX = fmaxf(maxX, X);
            minY = fminf(minY, Y); maxY = fmaxf(maxY, Y);
        }

        float lM = fmaxf(rintf(minX), 0.0f);
        float rM = fminf(rintf(maxX), (float)(NUM_W - 1));
        float tM = fmaxf(rintf(minY), 0.0f);
        float bM = fminf(rintf(maxY), (float)(NUM_H - 1));

        float bcx = __fmul_rn(__fadd_rn(lM, rM), 0.5f);
        float bcy = __fmul_rn(__fadd_rn(tM, bM), 0.5f);

        float flx = floorf(bcx);
        float fly = floorf(bcy);
        int il = (int)flx;
        int it = (int)fly;
        int ir = (int)ceilf(bcx);
        int ib = (int)ceilf(bcy);
        float rx = __fsub_rn(bcx, flx);
        float ry = __fsub_rn(bcy, fly);

        float omrx = __fsub_rn(1.0f, rx);
        float omry = __fsub_rn(1.0f, ry);
        float wlt = __fmul_rn(omrx, omry);
        float wrt = __fmul_rn(rx,   omry);
        float wrb = __fmul_rn(rx,   ry);
        float wlb = __fmul_rn(omrx, ry);

        bool vl = (il >= 0) && (il < NUM_W);
        bool vr = (ir >= 0) && (ir < NUM_W);
        bool vt = (it >= 0) && (it < NUM_H);
        bool vb = (ib >= 0) && (ib < NUM_H);

        int cl = min(max(il, 0), NUM_W - 1);
        int cr = min(max(ir, 0), NUM_W - 1);
        int ct = min(max(it, 0), NUM_H - 1);
        int cb = min(max(ib, 0), NUM_H - 1);

        float Wlt = (vt && vl) ? wlt : 0.0f;
        float Wrt = (vt && vr) ? wrt : 0.0f;
        float Wrb = (vb && vr) ? wrb : 0.0f;
        float Wlb = (vb && vl) ? wlb : 0.0f;

        int ot  = ct * NUM_W;
        int ob2 = cb * NUM_W;
        int cl4 = cl & ~3;
        int j   = cl & 3;
        bool samecol = (cr == cl);

        float wt[4] = {0.f, 0.f, 0.f, 0.f};
        float wb[4] = {0.f, 0.f, 0.f, 0.f};
        float wxt = 0.f, wxb = 0.f;

        wt[j] = Wlt;
        wb[j] = Wlb;
        if (samecol) {
            wt[j] += Wrt;     // exact: rt == lt value
            wb[j] += Wrb;
        } else if (j < 3) {
            wt[j + 1] = Wrt;
            wb[j + 1] = Wrb;
        } else {
            wxt = Wrt;
            wxb = Wrb;
        }

        bool topn = (Wlt != 0.0f) || (Wrt != 0.0f);
        bool botn = (Wlb != 0.0f) || (Wrb != 0.0f);
        bool xt   = topn && (wxt != 0.0f);
        bool xb   = botn && (wxb != 0.0f);

        s_wt[tid] = make_float4(wt[0], wt[1], wt[2], wt[3]);
        s_wb[tid] = make_float4(wb[0], wb[1], wb[2], wb[3]);
        s_wx[tid] = make_float2(wxt, wxb);

        int4 o;
        o.x = ot  + cl4;
        o.y = ob2 + cl4;
        o.z = ot  + cr;
        o.w = ob2 + cr;
        s_off[tid] = o;

        s_meta[tid] = (topn ? MB_TOPN : 0) | (botn ? MB_BOTN : 0)
                    | (xt ? MB_XT : 0) | (xb ? MB_XB : 0);
    }
    __syncthreads();

    if (tid >= 5 * NBIN) return;   // 245 active threads

    const int bin = tid % NBIN;
    const int c0  = tid / NBIN;    // 0..4

    const int4   o   = s_off[bin];
    const float4 wt4 = s_wt[bin];
    const float4 wb4 = s_wb[bin];
    const float2 wx  = s_wx[bin];
    const int    m   = s_meta[bin];
    const bool topn = (m & MB_TOPN) != 0;
    const bool botn = (m & MB_BOTN) != 0;
    const bool xt   = (m & MB_XT)   != 0;
    const bool xb   = (m & MB_XB)   != 0;

    const int cbeg = half * C_HALF + c0;

    // Pointer streams: advance by 5 channel planes per iteration.
    const float* fb = x + (size_t)(roi >> 9) * CHW + (size_t)cbeg * HW;
    const float* pT  = fb + o.x;
    const float* pB  = fb + o.y;
    const float* pXT = fb + o.z;
    const float* pXB = fb + o.w;
    float* po = out + (size_t)roi * (NUM_C * NBIN) + (size_t)cbeg * NBIN + bin;

    const ptrdiff_t stepIn  = 5 * HW;
    const ptrdiff_t stepOut = 5 * NBIN;

    // channels cbeg, cbeg+5, ... < half*128+128  ->  ceil((128-c0)/5)
    const int iters = (C_HALF - c0 + 4) / 5;   // 25 or 26

    #pragma unroll 4
    for (int i = 0; i < iters; ++i) {
        float4 t4 = make_float4(0.f, 0.f, 0.f, 0.f);
        float4 b4 = make_float4(0.f, 0.f, 0.f, 0.f);
        float rtx = 0.f, rbx = 0.f;
        if (topn) t4 = *reinterpret_cast<const float4*>(pT);
        if (botn) b4 = *reinterpret_cast<const float4*>(pB);
        if (xt)   rtx = *pXT;
        if (xb)   rbx = *pXB;

        float v = t4.x * wt4.x + t4.y * wt4.y + t4.z * wt4.z + t4.w * wt4.w
                + b4.x * wb4.x + b4.y * wb4.y + b4.z * wb4.z + b4.w * wb4.w
                + rtx * wx.x + rbx * wx.y;
        *po = fmaxf(v, 0.0f);

        pT += stepIn; pB += stepIn; pXT += stepIn; pXB += stepIn;
        po += stepOut;
    }
}

extern "C" void kernel_launch(void* const* d_in, const int* in_sizes, int n_in,
                              void* d_out, int out_size) {
    const float* x     = (const float*)d_in[0];   // (2,256,256,256) f32
    const float* boxes = (const float*)d_in[1];   // (2,512,5) f32
    float* out = (float*)d_out;                   // (1024,256,7,7) f32
    (void)in_sizes; (void)n_in; (void)out_size;

    rroi_pool_kernel<<<NUM_B * NUM_N * 2, 256>>>(x, boxes, out);
}

// round 6
// speedup vs baseline: 1.0003x; 1.0003x over previous
#include <cuda_runtime.h>
#include <math.h>

#define NUM_B 2
#define NUM_C 256
#define NUM_H 256
#define NUM_W 256
#define NUM_N 512
#define OUT_H 7
#define OUT_W 7
#define NBIN 49
#define HW (NUM_H * NUM_W)
#define CHW (NUM_C * HW)
#define C_HALF 128

#define MB_TOPN 1
#define MB_BOTN 2
#define MB_XT   4
#define MB_XB   8

__global__ __launch_bounds__(256) void rroi_pool_kernel(
    const float* __restrict__ x,
    const float* __restrict__ boxes,
    float* __restrict__ out)
{
    __shared__ int4   s_off[NBIN];  // top f4 off, bottom f4 off, top extra, bottom extra
    __shared__ float4 s_wt[NBIN];   // lane weights for top float4
    __shared__ float4 s_wb[NBIN];   // lane weights for bottom float4
    __shared__ float2 s_wx[NBIN];   // scalar fallback weights (top, bottom)
    __shared__ int    s_meta[NBIN];

    const int roi  = blockIdx.x >> 1;
    const int half = blockIdx.x & 1;
    const int tid  = threadIdx.x;

    if (tid < NBIN) {
        const float* bx = boxes + roi * 5;
        float cx  = __fmul_rn(bx[0], 0.25f);
        float cy  = __fmul_rn(bx[1], 0.25f);
        float w   = __fmul_rn(bx[2], 0.25f);
        float h   = __fmul_rn(bx[3], 0.25f);
        float ang = __fmul_rn(bx[4], 0.017453292519943295f);

        float Sx = __fdiv_rn(w, 7.0f);
        float Sy = __fdiv_rn(h, 7.0f);
        float ca = cosf(ang);
        float sa = sinf(ang);

        const float dxc = -3.5f;
        const float dyc = -3.5f;

        float M00 = __fmul_rn(ca, Sx);
        float M01 = __fmul_rn(sa, Sy);
        float M02 = __fadd_rn(__fadd_rn(__fmul_rn(__fmul_rn(ca, Sx), dxc),
                                        __fmul_rn(__fmul_rn(sa, Sy), dyc)), cx);
        float M10 = __fmul_rn(-sa, Sx);
        float M11 = __fmul_rn(ca, Sy);
        float M12 = __fadd_rn(__fadd_rn(__fmul_rn(__fmul_rn(-sa, Sx), dxc),
                                        __fmul_rn(__fmul_rn(ca, Sy), dyc)), cy);

        int ph = tid / OUT_W;
        int pw = tid - ph * OUT_W;

        const float offx[4] = {0.f, 0.f, 1.f, 1.f};
        const float offy[4] = {0.f, 1.f, 0.f, 1.f};

        float minX =  3.0e38f, maxX = -3.0e38f;
        float minY =  3.0e38f, maxY = -3.0e38f;
        #pragma unroll
        for (int k = 0; k < 4; ++k) {
            float pwc = (float)pw + offx[k];
            float phc = (float)ph + offy[k];
            float X = __fadd_rn(__fadd_rn(__fmul_rn(M00, pwc), __fmul_rn(M01, phc)), M02);
            float Y = __fadd_rn(__fadd_rn(__fmul_rn(M10, pwc), __fmul_rn(M11, phc)), M12);
            minX = fminf(minX, X); maxX = fmaxf(maxX, X);
            minY = fminf(minY, Y); maxY = fmaxf(maxY, Y);
        }

        float lM = fmaxf(rintf(minX), 0.0f);
        float rM = fminf(rintf(maxX), (float)(NUM_W - 1));
        float tM = fmaxf(rintf(minY), 0.0f);
        float bM = fminf(rintf(maxY), (float)(NUM_H - 1));

        float bcx = __fmul_rn(__fadd_rn(lM, rM), 0.5f);
        float bcy = __fmul_rn(__fadd_rn(tM, bM), 0.5f);

        float flx = floorf(bcx);
        float fly = floorf(bcy);
        int il = (int)flx;
        int it = (int)fly;
        int ir = (int)ceilf(bcx);
        int ib = (int)ceilf(bcy);
        float rx = __fsub_rn(bcx, flx);
        float ry = __fsub_rn(bcy, fly);

        float omrx = __fsub_rn(1.0f, rx);
        float omry = __fsub_rn(1.0f, ry);
        float wlt = __fmul_rn(omrx, omry);
        float wrt = __fmul_rn(rx,   omry);
        float wrb = __fmul_rn(rx,   ry);
        float wlb = __fmul_rn(omrx, ry);

        bool vl = (il >= 0) && (il < NUM_W);
        bool vr = (ir >= 0) && (ir < NUM_W);
        bool vt = (it >= 0) && (it < NUM_H);
        bool vb = (ib >= 0) && (ib < NUM_H);

        int cl = min(max(il, 0), NUM_W - 1);
        int cr = min(max(ir, 0), NUM_W - 1);
        int ct = min(max(it, 0), NUM_H - 1);
        int cb = min(max(ib, 0), NUM_H - 1);

        float Wlt = (vt && vl) ? wlt : 0.0f;
        float Wrt = (vt && vr) ? wrt : 0.0f;
        float Wrb = (vb && vr) ? wrb : 0.0f;
        float Wlb = (vb && vl) ? wlb : 0.0f;

        int ot  = ct * NUM_W;
        int ob2 = cb * NUM_W;
        int cl4 = cl & ~3;
        int j   = cl & 3;
        bool samecol = (cr == cl);

        float wt[4] = {0.f, 0.f, 0.f, 0.f};
        float wb[4] = {0.f, 0.f, 0.f, 0.f};
        float wxt = 0.f, wxb = 0.f;

        wt[j] = Wlt;
        wb[j] = Wlb;
        if (samecol) {
            wt[j] += Wrt;     // exact: rt == lt value
            wb[j] += Wrb;
        } else if (j < 3) {
            wt[j + 1] = Wrt;
            wb[j + 1] = Wrb;
        } else {
            wxt = Wrt;
            wxb = Wrb;
        }

        bool topn = (Wlt != 0.0f) || (Wrt != 0.0f);
        bool botn = (Wlb != 0.0f) || (Wrb != 0.0f);
        bool xt   = topn && (wxt != 0.0f);
        bool xb   = botn && (wxb != 0.0f);

        s_wt[tid] = make_float4(wt[0], wt[1], wt[2], wt[3]);
        s_wb[tid] = make_float4(wb[0], wb[1], wb[2], wb[3]);
        s_wx[tid] = make_float2(wxt, wxb);

        int4 o;
        o.x = ot  + cl4;
        o.y = ob2 + cl4;
        o.z = ot  + cr;
        o.w = ob2 + cr;
        s_off[tid] = o;

        s_meta[tid] = (topn ? MB_TOPN : 0) | (botn ? MB_BOTN : 0)
                    | (xt ? MB_XT : 0) | (xb ? MB_XB : 0);
    }
    __syncthreads();

    if (tid >= 5 * NBIN) return;   // 245 active threads

    const int bin = tid % NBIN;
    const int c0  = tid / NBIN;    // 0..4

    const int4   o   = s_off[bin];
    const float4 wt4 = s_wt[bin];
    const float4 wb4 = s_wb[bin];
    const float2 wx  = s_wx[bin];
    const int    m   = s_meta[bin];
    const bool topn = (m & MB_TOPN) != 0;
    const bool botn = (m & MB_BOTN) != 0;
    const bool xt   = (m & MB_XT)   != 0;
    const bool xb   = (m & MB_XB)   != 0;

    const float* fb = x + (size_t)(roi >> 9) * CHW;
    float* ob = out + (size_t)roi * (NUM_C * NBIN) + bin;

    const int cbeg = half * C_HALF + c0;
    const int cend = half * C_HALF + C_HALF;
    const int iters = (C_HALF - c0 + 4) / 5;   // 25 or 26

    int c = cbeg;
    int i = 0;

    // Main batched loop: load phase (8 LDG.128 + rare scalars), then compute.
    for (; i + 4 <= iters; i += 4, c += 20) {
        float4 t[4], b[4];
        float rtx[4], rbx[4];

        #pragma unroll
        for (int k = 0; k < 4; ++k) {
            const float* pc = fb + (size_t)(c + 5 * k) * HW;
            t[k] = make_float4(0.f, 0.f, 0.f, 0.f);
            b[k] = make_float4(0.f, 0.f, 0.f, 0.f);
            rtx[k] = 0.f; rbx[k] = 0.f;
            if (topn) t[k] = *reinterpret_cast<const float4*>(pc + o.x);
            if (botn) b[k] = *reinterpret_cast<const float4*>(pc + o.y);
            if (xt)   rtx[k] = pc[o.z];
            if (xb)   rbx[k] = pc[o.w];
        }

        #pragma unroll
        for (int k = 0; k < 4; ++k) {
            float v = t[k].x * wt4.x + t[k].y * wt4.y + t[k].z * wt4.z + t[k].w * wt4.w
                    + b[k].x * wb4.x + b[k].y * wb4.y + b[k].z * wb4.z + b[k].w * wb4.w
                    + rtx[k] * wx.x + rbx[k] * wx.y;
            ob[(size_t)(c + 5 * k) * NBIN] = fmaxf(v, 0.0f);
        }
    }

    // Remainder
    for (; i < iters; ++i, c += 5) {
        const float* pc = fb + (size_t)c * HW;
        float4 t4 = make_float4(0.f, 0.f, 0.f, 0.f);
        float4 b4 = make_float4(0.f, 0.f, 0.f, 0.f);
        float rt1 = 0.f, rb1 = 0.f;
        if (topn) t4 = *reinterpret_cast<const float4*>(pc + o.x);
        if (botn) b4 = *reinterpret_cast<const float4*>(pc + o.y);
        if (xt)   rt1 = pc[o.z];
        if (xb)   rb1 = pc[o.w];

        float v = t4.x * wt4.x + t4.y * wt4.y + t4.z * wt4.z + t4.w * wt4.w
                + b4.x * wb4.x + b4.y * wb4.y + b4.z * wb4.z + b4.w * wb4.w
                + rt1 * wx.x + rb1 * wx.y;
        ob[(size_t)c * NBIN] = fmaxf(v, 0.0f);
    }
}

extern "C" void kernel_launch(void* const* d_in, const int* in_sizes, int n_in,
                              void* d_out, int out_size) {
    const float* x     = (const float*)d_in[0];   // (2,256,256,256) f32
    const float* boxes = (const float*)d_in[1];   // (2,512,5) f32
    float* out = (float*)d_out;                   // (1024,256,7,7) f32
    (void)in_sizes; (void)n_in; (void)out_size;

    rroi_pool_kernel<<<NUM_B * NUM_N * 2, 256>>>(x, boxes, out);
}

// round 7
// speedup vs baseline: 1.0794x; 1.0791x over previous
#include <cuda_runtime.h>
#include <math.h>

#define NUM_B 2
#define NUM_C 256
#define NUM_H 256
#define NUM_W 256
#define NUM_N 512
#define OUT_H 7
#define OUT_W 7
#define NBIN 49
#define HW (NUM_H * NUM_W)
#define CHW (NUM_C * HW)
#define C_HALF 128

#define MB_TOPN 1
#define MB_BOTN 2
#define MB_XT   4
#define MB_XB   8

__global__ __launch_bounds__(256, 6) void rroi_pool_kernel(
    const float* __restrict__ x,
    const float* __restrict__ boxes,
    float* __restrict__ out)
{
    __shared__ int4   s_off[NBIN];  // top f4 off, bottom f4 off, top extra, bottom extra
    __shared__ float4 s_wt[NBIN];   // lane weights for top float4
    __shared__ float4 s_wb[NBIN];   // lane weights for bottom float4
    __shared__ float2 s_wx[NBIN];   // scalar fallback weights (top, bottom)
    __shared__ int    s_meta[NBIN];

    const int roi  = blockIdx.x >> 1;
    const int half = blockIdx.x & 1;
    const int tid  = threadIdx.x;

    if (tid < NBIN) {
        const float* bx = boxes + roi * 5;
        float cx  = __fmul_rn(bx[0], 0.25f);
        float cy  = __fmul_rn(bx[1], 0.25f);
        float w   = __fmul_rn(bx[2], 0.25f);
        float h   = __fmul_rn(bx[3], 0.25f);
        float ang = __fmul_rn(bx[4], 0.017453292519943295f);

        float Sx = __fdiv_rn(w, 7.0f);
        float Sy = __fdiv_rn(h, 7.0f);
        float ca = cosf(ang);
        float sa = sinf(ang);

        const float dxc = -3.5f;
        const float dyc = -3.5f;

        float M00 = __fmul_rn(ca, Sx);
        float M01 = __fmul_rn(sa, Sy);
        float M02 = __fadd_rn(__fadd_rn(__fmul_rn(__fmul_rn(ca, Sx), dxc),
                                        __fmul_rn(__fmul_rn(sa, Sy), dyc)), cx);
        float M10 = __fmul_rn(-sa, Sx);
        float M11 = __fmul_rn(ca, Sy);
        float M12 = __fadd_rn(__fadd_rn(__fmul_rn(__fmul_rn(-sa, Sx), dxc),
                                        __fmul_rn(__fmul_rn(ca, Sy), dyc)), cy);

        int ph = tid / OUT_W;
        int pw = tid - ph * OUT_W;

        const float offx[4] = {0.f, 0.f, 1.f, 1.f};
        const float offy[4] = {0.f, 1.f, 0.f, 1.f};

        float minX =  3.0e38f, maxX = -3.0e38f;
        float minY =  3.0e38f, maxY = -3.0e38f;
        #pragma unroll
        for (int k = 0; k < 4; ++k) {
            float pwc = (float)pw + offx[k];
            float phc = (float)ph + offy[k];
            float X = __fadd_rn(__fadd_rn(__fmul_rn(M00, pwc), __fmul_rn(M01, phc)), M02);
            float Y = __fadd_rn(__fadd_rn(__fmul_rn(M10, pwc), __fmul_rn(M11, phc)), M12);
            minX = fminf(minX, X); maxX = fmaxf(maxX, X);
            minY = fminf(minY, Y); maxY = fmaxf(maxY, Y);
        }

        float lM = fmaxf(rintf(minX), 0.0f);
        float rM = fminf(rintf(maxX), (float)(NUM_W - 1));
        float tM = fmaxf(rintf(minY), 0.0f);
        float bM = fminf(rintf(maxY), (float)(NUM_H - 1));

        float bcx = __fmul_rn(__fadd_rn(lM, rM), 0.5f);
        float bcy = __fmul_rn(__fadd_rn(tM, bM), 0.5f);

        float flx = floorf(bcx);
        float fly = floorf(bcy);
        int il = (int)flx;
        int it = (int)fly;
        int ir = (int)ceilf(bcx);
        int ib = (int)ceilf(bcy);
        float rx = __fsub_rn(bcx, flx);
        float ry = __fsub_rn(bcy, fly);

        float omrx = __fsub_rn(1.0f, rx);
        float omry = __fsub_rn(1.0f, ry);
        float wlt = __fmul_rn(omrx, omry);
        float wrt = __fmul_rn(rx,   omry);
        float wrb = __fmul_rn(rx,   ry);
        float wlb = __fmul_rn(omrx, ry);

        bool vl = (il >= 0) && (il < NUM_W);
        bool vr = (ir >= 0) && (ir < NUM_W);
        bool vt = (it >= 0) && (it < NUM_H);
        bool vb = (ib >= 0) && (ib < NUM_H);

        int cl = min(max(il, 0), NUM_W - 1);
        int cr = min(max(ir, 0), NUM_W - 1);
        int ct = min(max(it, 0), NUM_H - 1);
        int cb = min(max(ib, 0), NUM_H - 1);

        float Wlt = (vt && vl) ? wlt : 0.0f;
        float Wrt = (vt && vr) ? wrt : 0.0f;
        float Wrb = (vb && vr) ? wrb : 0.0f;
        float Wlb = (vb && vl) ? wlb : 0.0f;

        int ot  = ct * NUM_W;
        int ob2 = cb * NUM_W;
        int cl4 = cl & ~3;
        int j   = cl & 3;
        bool samecol = (cr == cl);

        float wt[4] = {0.f, 0.f, 0.f, 0.f};
        float wb[4] = {0.f, 0.f, 0.f, 0.f};
        float wxt = 0.f, wxb = 0.f;

        wt[j] = Wlt;
        wb[j] = Wlb;
        if (samecol) {
            wt[j] += Wrt;     // exact: rt == lt value
            wb[j] += Wrb;
        } else if (j < 3) {
            wt[j + 1] = Wrt;
            wb[j + 1] = Wrb;
        } else {
            wxt = Wrt;
            wxb = Wrb;
        }

        bool topn = (Wlt != 0.0f) || (Wrt != 0.0f);
        bool botn = (Wlb != 0.0f) || (Wrb != 0.0f);
        bool xt   = topn && (wxt != 0.0f);
        bool xb   = botn && (wxb != 0.0f);

        s_wt[tid] = make_float4(wt[0], wt[1], wt[2], wt[3]);
        s_wb[tid] = make_float4(wb[0], wb[1], wb[2], wb[3]);
        s_wx[tid] = make_float2(wxt, wxb);

        int4 o;
        o.x = ot  + cl4;
        o.y = ob2 + cl4;
        o.z = ot  + cr;
        o.w = ob2 + cr;
        s_off[tid] = o;

        s_meta[tid] = (topn ? MB_TOPN : 0) | (botn ? MB_BOTN : 0)
                    | (xt ? MB_XT : 0) | (xb ? MB_XB : 0);
    }
    __syncthreads();

    if (tid >= 5 * NBIN) return;   // 245 active threads

    const int bin = tid % NBIN;
    const int c0  = tid / NBIN;    // 0..4

    const int4   o   = s_off[bin];
    const float4 wt4 = s_wt[bin];
    const float4 wb4 = s_wb[bin];
    const float2 wx  = s_wx[bin];
    const int    m   = s_meta[bin];
    const bool topn = (m & MB_TOPN) != 0;
    const bool botn = (m & MB_BOTN) != 0;
    const bool xt   = (m & MB_XT)   != 0;
    const bool xb   = (m & MB_XB)   != 0;

    const float* fb = x + (size_t)(roi >> 9) * CHW;
    float* ob = out + (size_t)roi * (NUM_C * NBIN) + bin;

    const int cbeg = half * C_HALF + c0;
    const int cend = half * C_HALF + C_HALF;

    #pragma unroll 4
    for (int c = cbeg; c < cend; c += 5) {
        const float* pc = fb + (size_t)c * HW;

        float4 t4 = make_float4(0.f, 0.f, 0.f, 0.f);
        float4 b4 = make_float4(0.f, 0.f, 0.f, 0.f);
        float rtx = 0.f, rbx = 0.f;
        if (topn) t4 = *reinterpret_cast<const float4*>(pc + o.x);
        if (botn) b4 = *reinterpret_cast<const float4*>(pc + o.y);
        if (xt)   rtx = pc[o.z];
        if (xb)   rbx = pc[o.w];

        float v = t4.x * wt4.x + t4.y * wt4.y + t4.z * wt4.z + t4.w * wt4.w
                + b4.x * wb4.x + b4.y * wb4.y + b4.z * wb4.z + b4.w * wb4.w
                + rtx * wx.x + rbx * wx.y;
        ob[(size_t)c * NBIN] = fmaxf(v, 0.0f);
    }
}

extern "C" void kernel_launch(void* const* d_in, const int* in_sizes, int n_in,
                              void* d_out, int out_size) {
    const float* x     = (const float*)d_in[0];   // (2,256,256,256) f32
    const float* boxes = (const float*)d_in[1];   // (2,512,5) f32
    float* out = (float*)d_out;                   // (1024,256,7,7) f32
    (void)in_sizes; (void)n_in; (void)out_size;

    rroi_pool_kernel<<<NUM_B * NUM_N * 2, 256>>>(x, boxes, out);
}

// round 8
// speedup vs baseline: 1.2638x; 1.1708x over previous
#include <cuda_runtime.h>
#include <math.h>

#define NUM_B 2
#define NUM_C 256
#define NUM_H 256
#define NUM_W 256
#define NUM_N 512
#define OUT_H 7
#define OUT_W 7
#define NBIN 49
#define HW (NUM_H * NUM_W)
#define CHW (NUM_C * HW)
#define C_HALF 128
#define SOUT_PAD 133   // gcd(133 mod 32, 32) = 1 -> conflict-free transpose-read

// NHWC copy of x: xT[b][y][x][c]
__device__ float xT_buf[(size_t)NUM_B * NUM_H * NUM_W * NUM_C];

// ---------------------------------------------------------------------------
// Kernel A: NCHW -> NHWC transpose. grid (W/32, C/32, B*H), block (32, 8).
// ---------------------------------------------------------------------------
__global__ __launch_bounds__(256) void transpose_kernel(const float* __restrict__ x)
{
    __shared__ float tile[32][33];

    const int w0 = blockIdx.x * 32;
    const int c0 = blockIdx.y * 32;
    const int bh = blockIdx.z;           // b*256 + h
    const int b  = bh >> 8;
    const int h  = bh & 255;
    const int tx = threadIdx.x;          // 0..31
    const int ty = threadIdx.y;          // 0..7

    // load: rows = channels, cols = w (coalesced along w)
    const float* src = x + (((size_t)b * NUM_C + c0) * NUM_H + h) * NUM_W + w0;
    #pragma unroll
    for (int i = 0; i < 4; ++i) {
        int cl = ty + 8 * i;
        tile[cl][tx] = src[(size_t)cl * HW + tx];
    }
    __syncthreads();

    // write: rows = w, cols = channels (coalesced along c)
    float* dst = xT_buf + (((size_t)b * NUM_H + h) * NUM_W + w0) * NUM_C + c0;
    #pragma unroll
    for (int i = 0; i < 4; ++i) {
        int wl = ty + 8 * i;
        dst[(size_t)wl * NUM_C + tx] = tile[tx][wl];
    }
}

// ---------------------------------------------------------------------------
// Kernel B: RROI pool from NHWC. grid = 2048 (roi * 2 halves), block 256.
// ---------------------------------------------------------------------------
__global__ __launch_bounds__(256) void rroi_pool_kernel(
    const float* __restrict__ boxes,
    float* __restrict__ out)
{
    __shared__ int   s_pos[NBIN][4];        // clamped corner spatial idx y*256+x
    __shared__ float s_wgt[NBIN][4];        // validity-folded weights lt,rt,rb,lb
    __shared__ float s_out[NBIN][SOUT_PAD]; // [bin][channel-within-half]

    const int roi  = blockIdx.x >> 1;
    const int half = blockIdx.x & 1;
    const int tid  = threadIdx.x;

    if (tid < NBIN) {
        const float* bx = boxes + roi * 5;
        float cx  = __fmul_rn(bx[0], 0.25f);
        float cy  = __fmul_rn(bx[1], 0.25f);
        float w   = __fmul_rn(bx[2], 0.25f);
        float h   = __fmul_rn(bx[3], 0.25f);
        float ang = __fmul_rn(bx[4], 0.017453292519943295f);

        float Sx = __fdiv_rn(w, 7.0f);
        float Sy = __fdiv_rn(h, 7.0f);
        float ca = cosf(ang);
        float sa = sinf(ang);

        const float dxc = -3.5f;
        const float dyc = -3.5f;

        float M00 = __fmul_rn(ca, Sx);
        float M01 = __fmul_rn(sa, Sy);
        float M02 = __fadd_rn(__fadd_rn(__fmul_rn(__fmul_rn(ca, Sx), dxc),
                                        __fmul_rn(__fmul_rn(sa, Sy), dyc)), cx);
        float M10 = __fmul_rn(-sa, Sx);
        float M11 = __fmul_rn(ca, Sy);
        float M12 = __fadd_rn(__fadd_rn(__fmul_rn(__fmul_rn(-sa, Sx), dxc),
                                        __fmul_rn(__fmul_rn(ca, Sy), dyc)), cy);

        int ph = tid / OUT_W;
        int pw = tid - ph * OUT_W;

        const float offx[4] = {0.f, 0.f, 1.f, 1.f};
        const float offy[4] = {0.f, 1.f, 0.f, 1.f};

        float minX =  3.0e38f, maxX = -3.0e38f;
        float minY =  3.0e38f, maxY = -3.0e38f;
        #pragma unroll
        for (int k = 0; k < 4; ++k) {
            float pwc = (float)pw + offx[k];
            float phc = (float)ph + offy[k];
            float X = __fadd_rn(__fadd_rn(__fmul_rn(M00, pwc), __fmul_rn(M01, phc)), M02);
            float Y = __fadd_rn(__fadd_rn(__fmul_rn(M10, pwc), __fmul_rn(M11, phc)), M12);
            minX = fminf(minX, X); maxX = fmaxf(maxX, X);
            minY = fminf(minY, Y); maxY = fmaxf(maxY, Y);
        }

        float lM = fmaxf(rintf(minX), 0.0f);
        float rM = fminf(rintf(maxX), (float)(NUM_W - 1));
        float tM = fmaxf(rintf(minY), 0.0f);
        float bM = fminf(rintf(maxY), (float)(NUM_H - 1));

        float bcx = __fmul_rn(__fadd_rn(lM, rM), 0.5f);
        float bcy = __fmul_rn(__fadd_rn(tM, bM), 0.5f);

        float flx = floorf(bcx);
        float fly = floorf(bcy);
        int il = (int)flx;
        int it = (int)fly;
        int ir = (int)ceilf(bcx);
        int ib = (int)ceilf(bcy);
        float rx = __fsub_rn(bcx, flx);
        float ry = __fsub_rn(bcy, fly);

        float omrx = __fsub_rn(1.0f, rx);
        float omry = __fsub_rn(1.0f, ry);
        float wlt = __fmul_rn(omrx, omry);
        float wrt = __fmul_rn(rx,   omry);
        float wrb = __fmul_rn(rx,   ry);
        float wlb = __fmul_rn(omrx, ry);

        bool vl = (il >= 0) && (il < NUM_W);
        bool vr = (ir >= 0) && (ir < NUM_W);
        bool vt = (it >= 0) && (it < NUM_H);
        bool vb = (ib >= 0) && (ib < NUM_H);

        int cl = min(max(il, 0), NUM_W - 1);
        int cr = min(max(ir, 0), NUM_W - 1);
        int ct = min(max(it, 0), NUM_H - 1);
        int cb = min(max(ib, 0), NUM_H - 1);

        s_pos[tid][0] = ct * NUM_W + cl;
        s_pos[tid][1] = ct * NUM_W + cr;
        s_pos[tid][2] = cb * NUM_W + cr;
        s_pos[tid][3] = cb * NUM_W + cl;

        s_wgt[tid][0] = (vt && vl) ? wlt : 0.0f;
        s_wgt[tid][1] = (vt && vr) ? wrt : 0.0f;
        s_wgt[tid][2] = (vb && vr) ? wrb : 0.0f;
        s_wgt[tid][3] = (vb && vl) ? wlb : 0.0f;
    }
    __syncthreads();

    const int wid  = tid >> 5;
    const int lane = tid & 31;

    // base: xT[b][.][.][half*128 + lane*4]
    const float* base = xT_buf + ((size_t)(roi >> 9) * HW * NUM_C)
                      + half * C_HALF + lane * 4;

    for (int bin = wid; bin < NBIN; bin += 8) {
        float4 acc = make_float4(0.f, 0.f, 0.f, 0.f);
        #pragma unroll
        for (int k = 0; k < 4; ++k) {
            float wgt = s_wgt[bin][k];          // warp-uniform
            if (wgt != 0.0f) {
                float4 v = *reinterpret_cast<const float4*>(
                    base + (size_t)s_pos[bin][k] * NUM_C);
                acc.x += v.x * wgt;
                acc.y += v.y * wgt;
                acc.z += v.z * wgt;
                acc.w += v.w * wgt;
            }
        }
        s_out[bin][lane * 4 + 0] = fmaxf(acc.x, 0.0f);
        s_out[bin][lane * 4 + 1] = fmaxf(acc.y, 0.0f);
        s_out[bin][lane * 4 + 2] = fmaxf(acc.z, 0.0f);
        s_out[bin][lane * 4 + 3] = fmaxf(acc.w, 0.0f);
    }
    __syncthreads();

    // Coalesced write-out: 128 channels x 49 bins = 6272 floats per block.
    float* ob = out + (size_t)roi * (NUM_C * NBIN) + (size_t)half * C_HALF * NBIN;
    for (int i = tid; i < C_HALF * NBIN; i += 256) {
        int c   = i / NBIN;
        int bin = i - c * NBIN;
        ob[i] = s_out[bin][c];
    }
}

extern "C" void kernel_launch(void* const* d_in, const int* in_sizes, int n_in,
                              void* d_out, int out_size) {
    const float* x     = (const float*)d_in[0];   // (2,256,256,256) f32
    const float* boxes = (const float*)d_in[1];   // (2,512,5) f32
    float* out = (float*)d_out;                   // (1024,256,7,7) f32
    (void)in_sizes; (void)n_in; (void)out_size;

    dim3 tgrid(NUM_W / 32, NUM_C / 32, NUM_B * NUM_H);
    dim3 tblk(32, 8);
    transpose_kernel<<<tgrid, tblk>>>(x);

    rroi_pool_kernel<<<NUM_B * NUM_N * 2, 256>>>(boxes, out);
}

// round 9
// speedup vs baseline: 1.2676x; 1.0030x over previous
#include <cuda_runtime.h>
#include <math.h>

#define NUM_B 2
#define NUM_C 256
#define NUM_H 256
#define NUM_W 256
#define NUM_N 512
#define OUT_H 7
#define OUT_W 7
#define NBIN 49
#define HW (NUM_H * NUM_W)
#define CHW (NUM_C * HW)
#define C_HALF 128
#define SOUT_PAD 133

// NHWC copy of x: xT[b][y][x][c]
__device__ float xT_buf[(size_t)NUM_B * NUM_H * NUM_W * NUM_C];

// ---------------------------------------------------------------------------
// Kernel A: NCHW -> NHWC transpose, float4 both sides.
// grid (W/32, C/32, B*H), block (8, 32). Each thread moves one float4.
// ---------------------------------------------------------------------------
__global__ __launch_bounds__(256) void transpose_kernel(const float* __restrict__ x)
{
    __shared__ float tile[32][33];

    const int w0 = blockIdx.x * 32;
    const int c0 = blockIdx.y * 32;
    const int bh = blockIdx.z;           // b*256 + h
    const int b  = bh >> 8;
    const int h  = bh & 255;
    const int tx = threadIdx.x;          // 0..7  (float4 index)
    const int ty = threadIdx.y;          // 0..31

    // load: channel = c0+ty, 4 consecutive w. Coalesced LDG.128.
    const float* src = x + (((size_t)b * NUM_C + c0 + ty) * NUM_H + h) * NUM_W
                         + w0 + tx * 4;
    float4 v = *reinterpret_cast<const float4*>(src);
    tile[ty][tx * 4 + 0] = v.x;
    tile[ty][tx * 4 + 1] = v.y;
    tile[ty][tx * 4 + 2] = v.z;
    tile[ty][tx * 4 + 3] = v.w;
    __syncthreads();

    // store: w = w0+ty, 4 consecutive channels. Coalesced STG.128.
    float4 o;
    o.x = tile[tx * 4 + 0][ty];
    o.y = tile[tx * 4 + 1][ty];
    o.z = tile[tx * 4 + 2][ty];
    o.w = tile[tx * 4 + 3][ty];
    float* dst = xT_buf + (((size_t)b * NUM_H + h) * NUM_W + w0 + ty) * NUM_C
                        + c0 + tx * 4;
    *reinterpret_cast<float4*>(dst) = o;
}

// ---------------------------------------------------------------------------
// Kernel B: RROI pool from NHWC. grid = 2048 (roi * 2 halves), block 256.
// ---------------------------------------------------------------------------
__global__ __launch_bounds__(256) void rroi_pool_kernel(
    const float* __restrict__ boxes,
    float* __restrict__ out)
{
    __shared__ int   s_pos[NBIN][4];        // clamped corner spatial idx y*256+x
    __shared__ float s_wgt[NBIN][4];        // validity-folded weights lt,rt,rb,lb
    __shared__ float s_out[NBIN][SOUT_PAD]; // [bin][channel-within-half]

    const int roi  = blockIdx.x >> 1;
    const int half = blockIdx.x & 1;
    const int tid  = threadIdx.x;

    if (tid < NBIN) {
        const float* bx = boxes + roi * 5;
        float cx  = __fmul_rn(bx[0], 0.25f);
        float cy  = __fmul_rn(bx[1], 0.25f);
        float w   = __fmul_rn(bx[2], 0.25f);
        float h   = __fmul_rn(bx[3], 0.25f);
        float ang = __fmul_rn(bx[4], 0.017453292519943295f);

        float Sx = __fdiv_rn(w, 7.0f);
        float Sy = __fdiv_rn(h, 7.0f);
        float ca = cosf(ang);
        float sa = sinf(ang);

        const float dxc = -3.5f;
        const float dyc = -3.5f;

        float M00 = __fmul_rn(ca, Sx);
        float M01 = __fmul_rn(sa, Sy);
        float M02 = __fadd_rn(__fadd_rn(__fmul_rn(__fmul_rn(ca, Sx), dxc),
                                        __fmul_rn(__fmul_rn(sa, Sy), dyc)), cx);
        float M10 = __fmul_rn(-sa, Sx);
        float M11 = __fmul_rn(ca, Sy);
        float M12 = __fadd_rn(__fadd_rn(__fmul_rn(__fmul_rn(-sa, Sx), dxc),
                                        __fmul_rn(__fmul_rn(ca, Sy), dyc)), cy);

        int ph = tid / OUT_W;
        int pw = tid - ph * OUT_W;

        const float offx[4] = {0.f, 0.f, 1.f, 1.f};
        const float offy[4] = {0.f, 1.f, 0.f, 1.f};

        float minX =  3.0e38f, maxX = -3.0e38f;
        float minY =  3.0e38f, maxY = -3.0e38f;
        #pragma unroll
        for (int k = 0; k < 4; ++k) {
            float pwc = (float)pw + offx[k];
            float phc = (float)ph + offy[k];
            float X = __fadd_rn(__fadd_rn(__fmul_rn(M00, pwc), __fmul_rn(M01, phc)), M02);
            float Y = __fadd_rn(__fadd_rn(__fmul_rn(M10, pwc), __fmul_rn(M11, phc)), M12);
            minX = fminf(minX, X); maxX = fmaxf(maxX, X);
            minY = fminf(minY, Y); maxY = fmaxf(maxY, Y);
        }

        float lM = fmaxf(rintf(minX), 0.0f);
        float rM = fminf(rintf(maxX), (float)(NUM_W - 1));
        float tM = fmaxf(rintf(minY), 0.0f);
        float bM = fminf(rintf(maxY), (float)(NUM_H - 1));

        float bcx = __fmul_rn(__fadd_rn(lM, rM), 0.5f);
        float bcy = __fmul_rn(__fadd_rn(tM, bM), 0.5f);

        float flx = floorf(bcx);
        float fly = floorf(bcy);
        int il = (int)flx;
        int it = (int)fly;
        int ir = (int)ceilf(bcx);
        int ib = (int)ceilf(bcy);
        float rx = __fsub_rn(bcx, flx);
        float ry = __fsub_rn(bcy, fly);

        float omrx = __fsub_rn(1.0f, rx);
        float omry = __fsub_rn(1.0f, ry);
        float wlt = __fmul_rn(omrx, omry);
        float wrt = __fmul_rn(rx,   omry);
        float wrb = __fmul_rn(rx,   ry);
        float wlb = __fmul_rn(omrx, ry);

        bool vl = (il >= 0) && (il < NUM_W);
        bool vr = (ir >= 0) && (ir < NUM_W);
        bool vt = (it >= 0) && (it < NUM_H);
        bool vb = (ib >= 0) && (ib < NUM_H);

        int cl = min(max(il, 0), NUM_W - 1);
        int cr = min(max(ir, 0), NUM_W - 1);
        int ct = min(max(it, 0), NUM_H - 1);
        int cb = min(max(ib, 0), NUM_H - 1);

        s_pos[tid][0] = ct * NUM_W + cl;
        s_pos[tid][1] = ct * NUM_W + cr;
        s_pos[tid][2] = cb * NUM_W + cr;
        s_pos[tid][3] = cb * NUM_W + cl;

        s_wgt[tid][0] = (vt && vl) ? wlt : 0.0f;
        s_wgt[tid][1] = (vt && vr) ? wrt : 0.0f;
        s_wgt[tid][2] = (vb && vr) ? wrb : 0.0f;
        s_wgt[tid][3] = (vb && vl) ? wlb : 0.0f;
    }
    __syncthreads();

    const int wid  = tid >> 5;
    const int lane = tid & 31;

    // base: xT[b][.][.][half*128 + lane*4]
    const float* base = xT_buf + ((size_t)(roi >> 9) * HW * NUM_C)
                      + half * C_HALF + lane * 4;

    for (int bin = wid; bin < NBIN; bin += 8) {
        float4 acc = make_float4(0.f, 0.f, 0.f, 0.f);
        #pragma unroll
        for (int k = 0; k < 4; ++k) {
            float wgt = s_wgt[bin][k];          // warp-uniform
            if (wgt != 0.0f) {
                float4 v = *reinterpret_cast<const float4*>(
                    base + (size_t)s_pos[bin][k] * NUM_C);
                acc.x += v.x * wgt;
                acc.y += v.y * wgt;
                acc.z += v.z * wgt;
                acc.w += v.w * wgt;
            }
        }
        s_out[bin][lane * 4 + 0] = fmaxf(acc.x, 0.0f);
        s_out[bin][lane * 4 + 1] = fmaxf(acc.y, 0.0f);
        s_out[bin][lane * 4 + 2] = fmaxf(acc.z, 0.0f);
        s_out[bin][lane * 4 + 3] = fmaxf(acc.w, 0.0f);
    }
    __syncthreads();

    // Coalesced write-out: 128 channels x 49 bins = 6272 floats per block.
    float* ob = out + (size_t)roi * (NUM_C * NBIN) + (size_t)half * C_HALF * NBIN;
    for (int i = tid; i < C_HALF * NBIN; i += 256) {
        int c   = i / NBIN;
        int bin = i - c * NBIN;
        ob[i] = s_out[bin][c];
    }
}

extern "C" void kernel_launch(void* const* d_in, const int* in_sizes, int n_in,
                              void* d_out, int out_size) {
    const float* x     = (const float*)d_in[0];   // (2,256,256,256) f32
    const float* boxes = (const float*)d_in[1];   // (2,512,5) f32
    float* out = (float*)d_out;                   // (1024,256,7,7) f32
    (void)in_sizes; (void)n_in; (void)out_size;

    dim3 tgrid(NUM_W / 32, NUM_C / 32, NUM_B * NUM_H);
    dim3 tblk(8, 32);
    transpose_kernel<<<tgrid, tblk>>>(x);

    rroi_pool_kernel<<<NUM_B * NUM_N * 2, 256>>>(boxes, out);
}